// round 7
// baseline (speedup 1.0000x reference)
#include <cuda_runtime.h>
#include <cuda_bf16.h>

// MergedEmbeddingBag: weights [T,N,D] f32, indices [T,TOTAL] i32, offsets [T,B] i32
// out [T,B,D] f32, sum pooling. T=8, N=100000, D=128, B=16384, L=20.
//
// R7 = champion (R6) + micro-trims. Warp-per-bag, float4 __ldg gathers,
// shfl-distributed indices, no smem/no barriers, __stcs output.
// Kernel operates at the B300 LTS chip cap (~12.5 TB/s sustained SM<->L2):
// 1.39 GB compulsory traffic -> ~110 us floor. Loads remain __ldg intrinsics
// so ptxas front-batches all 20 LDG.128 (asm-volatile loads cost -17%, R5).

#define EB_T 8
#define EB_N 100000
#define EB_D 128
#define EB_B 16384
#define EB_LOG2_B 14
#define FULLMASK 0xffffffffu

__global__ void __launch_bounds__(256, 4)
merged_embeddingbag_warp_kernel(const float* __restrict__ weights,
                                const int* __restrict__ indices,
                                const int* __restrict__ offsets,
                                float* __restrict__ out,
                                int total_per_table)
{
    const int gw   = blockIdx.x * (blockDim.x >> 5) + (threadIdx.x >> 5); // (tbl,bag)
    const int lane = threadIdx.x & 31;
    const int tbl  = gw >> EB_LOG2_B;
    const int bag  = gw & (EB_B - 1);

    const int* off_t = offsets + tbl * EB_B;
    const int start = __ldg(&off_t[bag]);
    const int end   = (bag + 1 < EB_B) ? __ldg(&off_t[bag + 1]) : total_per_table;
    int cnt = end - start;
    if (cnt < 0) cnt = 0;

    const int* idx_t = indices + (size_t)tbl * total_per_table + start;
    const float4* __restrict__ w4 =
        (const float4*)(weights + (size_t)tbl * EB_N * EB_D);

    float4 acc0 = make_float4(0.f, 0.f, 0.f, 0.f);
    float4 acc1 = make_float4(0.f, 0.f, 0.f, 0.f);

    if (cnt == 20) {
        // Hot path (fixed L=20), no outer loop: one coalesced index load,
        // 20 compiler-batched independent LDG.128, dual accumulators so the
        // FADD chain never throttles load-queue drain.
        const int myidx = (lane < 20) ? __ldg(&idx_t[lane]) : 0;
        #pragma unroll
        for (int j = 0; j < 20; j += 2) {
            const int r0 = __shfl_sync(FULLMASK, myidx, j);
            const int r1 = __shfl_sync(FULLMASK, myidx, j + 1);
            const float4 v0 = __ldg(&w4[r0 * 32 + lane]);
            const float4 v1 = __ldg(&w4[r1 * 32 + lane]);
            acc0.x += v0.x; acc0.y += v0.y; acc0.z += v0.z; acc0.w += v0.w;
            acc1.x += v1.x; acc1.y += v1.y; acc1.z += v1.z; acc1.w += v1.w;
        }
    } else {
        // General path (any bag size).
        for (int base = 0; base < cnt; base += 32) {
            const int m = min(32, cnt - base);
            const int myidx = (lane < m) ? __ldg(&idx_t[base + lane]) : 0;
            for (int j = 0; j < m; j++) {
                const int r = __shfl_sync(FULLMASK, myidx, j);
                const float4 v = __ldg(&w4[r * 32 + lane]);
                acc0.x += v.x; acc0.y += v.y; acc0.z += v.z; acc0.w += v.w;
            }
        }
    }

    const float4 acc = make_float4(acc0.x + acc1.x, acc0.y + acc1.y,
                                   acc0.z + acc1.z, acc0.w + acc1.w);
    float4* __restrict__ o4 = (float4*)out;
    __stcs(&o4[(size_t)gw * 32 + lane], acc);   // evict-first: protect weight lines in L2
}

extern "C" void kernel_launch(void* const* d_in, const int* in_sizes, int n_in,
                              void* d_out, int out_size)
{
    const float* weights = (const float*)d_in[0];
    const int*   indices = (const int*)d_in[1];
    const int*   offsets = (const int*)d_in[2];
    float*       out     = (float*)d_out;

    const int total_per_table = in_sizes[1] / EB_T;  // 327680

    const int warps_per_block = 8;                   // 256 threads
    const int total_warps = EB_T * EB_B;             // 131072 bags
    const int nblocks = total_warps / warps_per_block;

    merged_embeddingbag_warp_kernel<<<nblocks, warps_per_block * 32>>>(
        weights, indices, offsets, out, total_per_table);
}